// round 3
// baseline (speedup 1.0000x reference)
#include <cuda_runtime.h>
#include <math.h>

#define T_ 256
#define B_ 8
#define D_ 128
#define L_ 2
#define ROWS (B_*T_)                  // 2048
#define STROW (L_*(D_*D_+D_)+1)       // 33025
#define YSZ (T_*B_*D_)                // 262144

// ---------------- scratch (device globals) ----------------------------------
__device__ float g_x  [ROWS*D_];
__device__ float g_Q  [ROWS*D_];
__device__ float g_K  [ROWS*D_];
__device__ float g_V  [ROWS*D_];
__device__ float g_att[ROWS*D_];

// ---------------- rotate (RoPE) + transpose z(T,B,D)->x(B,T,D) --------------
__global__ void rotate_kernel(const float* __restrict__ z,
                              const float* __restrict__ state,
                              float* __restrict__ x,
                              float* __restrict__ out_st)
{
    int idx = blockIdx.x * blockDim.x + threadIdx.x;   // B*T*64
    if (idx >= B_*T_*64) return;
    int j = idx & 63;
    int t = (idx >> 6) % T_;
    int b = idx / (64 * T_);
    float ts  = state[b*STROW + (STROW-1)];
    float pos = ts + (float)t;
    float freq = expf((float)(2*j) * (-logf(10000.0f) / (float)D_));
    float ang = pos * freq;
    float s, c;
    sincosf(ang, &s, &c);
    const float* zr = z + ((size_t)t*B_ + b) * D_;
    float*       xr = x + ((size_t)b*T_ + t) * D_;
    float a0 = zr[j], a1 = zr[j+64];
    xr[j]    = a0*c - a1*s;
    xr[j+64] = a1*c + a0*s;
    if (t == 0 && j == 0)
        out_st[b*STROW + (STROW-1)] = ts + (float)T_;
}

// ---------------- fused LN + QKV GEMM ---------------------------------------
// grid (ROWS/64, 6): y 0,1 -> Q (elu+1); 2,3 -> K (elu+1); 4,5 -> V.
// Each block LNs its 64-row x tile in smem, then GEMMs against a 64-col W slab.
__global__ void qkv_kernel(const float* __restrict__ x,
                           const float* __restrict__ Wq,
                           const float* __restrict__ Wk,
                           const float* __restrict__ Wv,
                           const float* __restrict__ lnw,
                           const float* __restrict__ lnb,
                           float* __restrict__ Qo,
                           float* __restrict__ Ko,
                           float* __restrict__ Vo)
{
    __shared__ float Xs[128][68];   // [k][row], LN'd in place
    __shared__ float Ws[16][68];    // [kk][col] staging
    __shared__ float mu[64], rsd[64];
    int tid = threadIdx.x;
    int rowBase = blockIdx.x * 64;
    int sel = blockIdx.y;
    const float* W; float* out; int act;
    if (sel < 2)      { W = Wq; out = Qo; act = 1; }
    else if (sel < 4) { W = Wk; out = Ko; act = 1; }
    else              { W = Wv; out = Vo; act = 0; }
    int colBase = (sel & 1) * 64;

    int r = tid >> 2, p = tid & 3;   // r 0..63, p*32 col chunk
    {
        const float* src = x + (size_t)(rowBase + r)*D_ + p*32;
        #pragma unroll
        for (int i = 0; i < 8; i++) {
            float4 v = *(const float4*)(src + i*4);
            int k = p*32 + i*4;
            Xs[k+0][r]=v.x; Xs[k+1][r]=v.y; Xs[k+2][r]=v.z; Xs[k+3][r]=v.w;
        }
    }
    __syncthreads();
    if (tid < 64) {
        float s = 0.f, s2 = 0.f;
        #pragma unroll 8
        for (int k = 0; k < 128; k++) { float v = Xs[k][tid]; s += v; s2 += v*v; }
        float m = s * (1.0f/128.0f);
        mu[tid] = m;
        rsd[tid] = rsqrtf(fmaxf(s2*(1.0f/128.0f) - m*m, 0.0f) + 1e-5f);
    }
    __syncthreads();
    {
        float m = mu[r], rr = rsd[r];
        #pragma unroll
        for (int i = 0; i < 32; i++) {
            int k = p*32 + i;
            Xs[k][r] = (Xs[k][r] - m) * rr * lnw[k] + lnb[k];
        }
    }
    __syncthreads();

    int tx = tid & 15, ty = tid >> 4;
    float acc[4][4] = {};
    for (int k0 = 0; k0 < 128; k0 += 16) {
        {
            int c = tid & 63, kq = (tid >> 6) * 4;
            float4 w4 = *(const float4*)(W + (size_t)(colBase + c)*D_ + k0 + kq);
            Ws[kq+0][c]=w4.x; Ws[kq+1][c]=w4.y; Ws[kq+2][c]=w4.z; Ws[kq+3][c]=w4.w;
        }
        __syncthreads();
        #pragma unroll
        for (int kk = 0; kk < 16; kk++) {
            float4 a4 = *(const float4*)&Xs[k0+kk][ty*4];
            float4 b4 = *(const float4*)&Ws[kk][tx*4];
            float a[4] = {a4.x, a4.y, a4.z, a4.w};
            float bb[4] = {b4.x, b4.y, b4.z, b4.w};
            #pragma unroll
            for (int i = 0; i < 4; i++)
                #pragma unroll
                for (int j = 0; j < 4; j++)
                    acc[i][j] += a[i] * bb[j];
        }
        __syncthreads();
    }
    #pragma unroll
    for (int i = 0; i < 4; i++) {
        int rr2 = rowBase + ty*4 + i;
        #pragma unroll
        for (int j = 0; j < 4; j++) {
            float v = acc[i][j];
            if (act == 1) v = (v > 0.f) ? v + 1.0f : expf(v);
            out[(size_t)rr2*D_ + colBase + tx*4 + j] = v;
        }
    }
}

// ---------------- fused attention ------------------------------------------
// O[t,l] = (sum_{u<=t} (Q[t].K[u]) V[u,l] + Q[t].S0[:,l]) /
//          (sum_{u<=t} Q[t].K[u] + Q[t].Z0 + 1e-5)
// grid (T/16, B), 256 threads. Never materializes A in HBM.
__global__ void attn_kernel(const float* __restrict__ Qg,
                            const float* __restrict__ Kg,
                            const float* __restrict__ Vg,
                            const float* __restrict__ state,
                            int layer,
                            float* __restrict__ O)
{
    __shared__ float Qs[16][132];
    __shared__ float Ku[32][132];
    __shared__ float Vs[32][132];
    __shared__ float As[32][20];    // [u][t]
    __shared__ float den[16];
    __shared__ float zs[32];
    int tid = threadIdx.x;
    int b = blockIdx.y;
    int tBase = blockIdx.x * 16;
    const float* Qb = Qg + (size_t)b*T_*D_;
    const float* Kb = Kg + (size_t)b*T_*D_;
    const float* Vb = Vg + (size_t)b*T_*D_;
    const float* S0 = state + (size_t)b*STROW + (size_t)layer*(D_*D_ + D_);
    const float* Z0 = S0 + D_*D_;

    {
        int r = tid >> 4, p = tid & 15;
        const float* src = Qb + (size_t)(tBase + r)*D_ + p*8;
        *(float4*)&Qs[r][p*8]   = *(const float4*)src;
        *(float4*)&Qs[r][p*8+4] = *(const float4*)(src + 4);
    }
    if (tid < 16) den[tid] = 0.0f;

    int tx = tid & 15, tyr = tid >> 4;
    float acc[8] = {};
    int nub = (tBase >> 5) + 1;
    for (int ub = 0; ub < nub; ub++) {
        int uBase = ub * 32;
        {
            int r = tid >> 3, p = tid & 7;
            const float* ks   = Kb + (size_t)(uBase + r)*D_ + p*16;
            const float* vsrc = Vb + (size_t)(uBase + r)*D_ + p*16;
            #pragma unroll
            for (int i = 0; i < 4; i++) {
                *(float4*)&Ku[r][p*16 + i*4] = *(const float4*)(ks + i*4);
                *(float4*)&Vs[r][p*16 + i*4] = *(const float4*)(vsrc + i*4);
            }
        }
        __syncthreads();
        {
            int txa = tid & 15, tya = tid >> 4;
            int u0 = txa * 2;
            float a0 = 0.f, a1 = 0.f;
            #pragma unroll 8
            for (int k = 0; k < 128; k += 4) {
                float4 q4  = *(const float4*)&Qs[tya][k];
                float4 k40 = *(const float4*)&Ku[u0][k];
                float4 k41 = *(const float4*)&Ku[u0+1][k];
                a0 += q4.x*k40.x + q4.y*k40.y + q4.z*k40.z + q4.w*k40.w;
                a1 += q4.x*k41.x + q4.y*k41.y + q4.z*k41.z + q4.w*k41.w;
            }
            if (ub == nub - 1) {
                int t = tBase + tya;
                if (uBase + u0     > t) a0 = 0.f;
                if (uBase + u0 + 1 > t) a1 = 0.f;
            }
            As[u0][tya]   = a0;
            As[u0+1][tya] = a1;
        }
        __syncthreads();
        if (tid < 16) {
            float s = 0.f;
            #pragma unroll
            for (int u = 0; u < 32; u++) s += As[u][tid];
            den[tid] += s;
        }
        #pragma unroll 4
        for (int u = 0; u < 32; u++) {
            float a = As[u][tyr];
            float4 b0 = *(const float4*)&Vs[u][tx*8];
            float4 b1 = *(const float4*)&Vs[u][tx*8+4];
            acc[0]+=a*b0.x; acc[1]+=a*b0.y; acc[2]+=a*b0.z; acc[3]+=a*b0.w;
            acc[4]+=a*b1.x; acc[5]+=a*b1.y; acc[6]+=a*b1.z; acc[7]+=a*b1.w;
        }
        __syncthreads();
    }
    // Q @ S0 staged 32 k-rows at a time (S0 only element-aligned -> scalar loads)
    for (int ksg = 0; ksg < 4; ksg++) {
        {
            int r = tid >> 3, p = tid & 7;
            const float* src = S0 + (size_t)(ksg*32 + r)*D_ + p*16;
            #pragma unroll
            for (int i = 0; i < 16; i++) Vs[r][p*16 + i] = src[i];
        }
        if (tid < 32) zs[tid] = Z0[ksg*32 + tid];
        __syncthreads();
        if (tid < 16) {
            float s = 0.f;
            #pragma unroll
            for (int kk = 0; kk < 32; kk++) s += Qs[tid][ksg*32 + kk] * zs[kk];
            den[tid] += s;
        }
        #pragma unroll 4
        for (int kk = 0; kk < 32; kk++) {
            float a = Qs[tyr][ksg*32 + kk];
            float4 b0 = *(const float4*)&Vs[kk][tx*8];
            float4 b1 = *(const float4*)&Vs[kk][tx*8+4];
            acc[0]+=a*b0.x; acc[1]+=a*b0.y; acc[2]+=a*b0.z; acc[3]+=a*b0.w;
            acc[4]+=a*b1.x; acc[5]+=a*b1.y; acc[6]+=a*b1.z; acc[7]+=a*b1.w;
        }
        __syncthreads();
    }
    float inv = 1.0f / (den[tyr] + 1e-5f);
    float* orow = O + ((size_t)b*T_ + tBase + tyr)*D_ + tx*8;
    #pragma unroll
    for (int j = 0; j < 8; j++) orow[j] = acc[j] * inv;
}

// ---------------- Sl = S0 + K^T@V ; Zl = Z0 + colsum(K) ----------------------
__global__ void state_kernel(const float* __restrict__ Km,
                             const float* __restrict__ V,
                             const float* __restrict__ state,
                             int layer,
                             float* __restrict__ stout)
{
    int b = blockIdx.z;
    int iBase = blockIdx.x * 64;
    int lBase = blockIdx.y * 64;
    const float* Kb = Km + (size_t)b * T_ * D_;
    const float* Vb = V  + (size_t)b * T_ * D_;
    __shared__ float Ks[16][64], Vs[16][64];
    __shared__ float zsum[64];
    int tid = threadIdx.x;
    int tx = tid & 15, ty = tid >> 4;
    int lkk = tid >> 4, lc = (tid & 15) * 4;
    if (tid < 64) zsum[tid] = 0.0f;
    float acc[4][4] = {};
    for (int k0 = 0; k0 < T_; k0 += 16) {
        *(float4*)&Ks[lkk][lc] = *(const float4*)(Kb + (size_t)(k0 + lkk)*D_ + iBase + lc);
        *(float4*)&Vs[lkk][lc] = *(const float4*)(Vb + (size_t)(k0 + lkk)*D_ + lBase + lc);
        __syncthreads();
        if (blockIdx.y == 0 && tid < 64) {
            float s = 0.0f;
            #pragma unroll
            for (int kk = 0; kk < 16; kk++) s += Ks[kk][tid];
            zsum[tid] += s;
        }
        #pragma unroll
        for (int kk = 0; kk < 16; kk++) {
            float a[4], bb[4];
            #pragma unroll
            for (int i = 0; i < 4; i++) a[i]  = Ks[kk][ty*4 + i];
            #pragma unroll
            for (int j = 0; j < 4; j++) bb[j] = Vs[kk][tx*4 + j];
            #pragma unroll
            for (int i = 0; i < 4; i++)
                #pragma unroll
                for (int j = 0; j < 4; j++)
                    acc[i][j] += a[i] * bb[j];
        }
        __syncthreads();
    }
    const float* S0 = state + (size_t)b * STROW + (size_t)layer * (D_*D_ + D_);
    float* dst = stout + (size_t)b * STROW + (size_t)layer * (D_*D_ + D_);
    #pragma unroll
    for (int i = 0; i < 4; i++) {
        int ii = iBase + ty*4 + i;
        #pragma unroll
        for (int j = 0; j < 4; j++) {
            int ll = lBase + tx*4 + j;
            dst[(size_t)ii*D_ + ll] = acc[i][j] + S0[(size_t)ii*D_ + ll];
        }
    }
    if (blockIdx.y == 0 && tid < 64) {
        int ii = iBase + tid;
        dst[D_*D_ + ii] = zsum[tid] + S0[D_*D_ + ii];
    }
}

// ---------------- fused FFN + skip: x = relu(relu(att W1'+b1)W2'+b2) + LN(x)scw'+scb
// grid ROWS/16 blocks, 256 threads. Reads & rewrites its own 16 rows of x.
__global__ void ffn_kernel(const float* __restrict__ att,
                           const float* __restrict__ w1, const float* __restrict__ b1,
                           const float* __restrict__ w2, const float* __restrict__ b2,
                           const float* __restrict__ scw, const float* __restrict__ scb,
                           const float* __restrict__ lnw, const float* __restrict__ lnb,
                           float* x)
{
    __shared__ float Aat[16][132];   // A operand (att tile, later LN'd x tile)
    __shared__ float Hs[16][132];    // h1
    __shared__ float Ws[16][132];    // weight chunk staging [kk][col]
    __shared__ float mu[16], rsd[16];
    int tid = threadIdx.x;
    int rowBase = blockIdx.x * 16;
    int tx = tid & 15, tyr = tid >> 4;
    int r = tid >> 4, p = tid & 15;

    {
        const float* src = att + (size_t)(rowBase + r)*D_ + p*8;
        *(float4*)&Aat[r][p*8]   = *(const float4*)src;
        *(float4*)&Aat[r][p*8+4] = *(const float4*)(src + 4);
    }
    __syncthreads();

    // ---- g1: h1 = relu(att @ w1^T + b1)
    float acc[8] = {};
    for (int k0 = 0; k0 < 128; k0 += 16) {
        {
            int c = tid >> 1, kq = (tid & 1) * 8;
            const float* wp = w1 + (size_t)c*D_ + k0 + kq;
            float4 wa = *(const float4*)wp, wb = *(const float4*)(wp + 4);
            Ws[kq+0][c]=wa.x; Ws[kq+1][c]=wa.y; Ws[kq+2][c]=wa.z; Ws[kq+3][c]=wa.w;
            Ws[kq+4][c]=wb.x; Ws[kq+5][c]=wb.y; Ws[kq+6][c]=wb.z; Ws[kq+7][c]=wb.w;
        }
        __syncthreads();
        #pragma unroll
        for (int kk = 0; kk < 16; kk++) {
            float a = Aat[tyr][k0 + kk];
            float4 c0 = *(const float4*)&Ws[kk][tx*8];
            float4 c1 = *(const float4*)&Ws[kk][tx*8+4];
            acc[0]+=a*c0.x; acc[1]+=a*c0.y; acc[2]+=a*c0.z; acc[3]+=a*c0.w;
            acc[4]+=a*c1.x; acc[5]+=a*c1.y; acc[6]+=a*c1.z; acc[7]+=a*c1.w;
        }
        __syncthreads();
    }
    #pragma unroll
    for (int j = 0; j < 8; j++)
        Hs[tyr][tx*8 + j] = fmaxf(acc[j] + b1[tx*8 + j], 0.0f);

    // ---- g2: t2 = relu(h1 @ w2^T + b2)
    float t2[8] = {};
    for (int k0 = 0; k0 < 128; k0 += 16) {
        {
            int c = tid >> 1, kq = (tid & 1) * 8;
            const float* wp = w2 + (size_t)c*D_ + k0 + kq;
            float4 wa = *(const float4*)wp, wb = *(const float4*)(wp + 4);
            Ws[kq+0][c]=wa.x; Ws[kq+1][c]=wa.y; Ws[kq+2][c]=wa.z; Ws[kq+3][c]=wa.w;
            Ws[kq+4][c]=wb.x; Ws[kq+5][c]=wb.y; Ws[kq+6][c]=wb.z; Ws[kq+7][c]=wb.w;
        }
        __syncthreads();
        #pragma unroll
        for (int kk = 0; kk < 16; kk++) {
            float a = Hs[tyr][k0 + kk];
            float4 c0 = *(const float4*)&Ws[kk][tx*8];
            float4 c1 = *(const float4*)&Ws[kk][tx*8+4];
            t2[0]+=a*c0.x; t2[1]+=a*c0.y; t2[2]+=a*c0.z; t2[3]+=a*c0.w;
            t2[4]+=a*c1.x; t2[5]+=a*c1.y; t2[6]+=a*c1.z; t2[7]+=a*c1.w;
        }
        __syncthreads();
    }
    #pragma unroll
    for (int j = 0; j < 8; j++) t2[j] = fmaxf(t2[j] + b2[tx*8 + j], 0.0f);

    // ---- load x tile, LN in place (reuse Aat)
    {
        const float* src = x + (size_t)(rowBase + r)*D_ + p*8;
        *(float4*)&Aat[r][p*8]   = *(const float4*)src;
        *(float4*)&Aat[r][p*8+4] = *(const float4*)(src + 4);
    }
    __syncthreads();
    if (tid < 16) {
        float s = 0.f, s2 = 0.f;
        #pragma unroll 8
        for (int k = 0; k < 128; k++) { float v = Aat[tid][k]; s += v; s2 += v*v; }
        float m = s * (1.0f/128.0f);
        mu[tid] = m;
        rsd[tid] = rsqrtf(fmaxf(s2*(1.0f/128.0f) - m*m, 0.0f) + 1e-5f);
    }
    __syncthreads();
    {
        float m = mu[r], rr = rsd[r];
        #pragma unroll
        for (int i = 0; i < 8; i++) {
            int k = p*8 + i;
            Aat[r][k] = (Aat[r][k] - m) * rr * lnw[k] + lnb[k];
        }
    }
    __syncthreads();

    // ---- g3: out = LN(x) @ scw^T + scb + t2  -> x
    float a3[8] = {};
    for (int k0 = 0; k0 < 128; k0 += 16) {
        {
            int c = tid >> 1, kq = (tid & 1) * 8;
            const float* wp = scw + (size_t)c*D_ + k0 + kq;
            float4 wa = *(const float4*)wp, wb = *(const float4*)(wp + 4);
            Ws[kq+0][c]=wa.x; Ws[kq+1][c]=wa.y; Ws[kq+2][c]=wa.z; Ws[kq+3][c]=wa.w;
            Ws[kq+4][c]=wb.x; Ws[kq+5][c]=wb.y; Ws[kq+6][c]=wb.z; Ws[kq+7][c]=wb.w;
        }
        __syncthreads();
        #pragma unroll
        for (int kk = 0; kk < 16; kk++) {
            float a = Aat[tyr][k0 + kk];
            float4 c0 = *(const float4*)&Ws[kk][tx*8];
            float4 c1 = *(const float4*)&Ws[kk][tx*8+4];
            a3[0]+=a*c0.x; a3[1]+=a*c0.y; a3[2]+=a*c0.z; a3[3]+=a*c0.w;
            a3[4]+=a*c1.x; a3[5]+=a*c1.y; a3[6]+=a*c1.z; a3[7]+=a*c1.w;
        }
        __syncthreads();
    }
    float* xo = x + (size_t)(rowBase + tyr)*D_ + tx*8;
    #pragma unroll
    for (int j = 0; j < 8; j++)
        xo[j] = a3[j] + scb[tx*8 + j] + t2[j];
}

// ---------------- unmap GEMM (scatter to y layout) ---------------------------
__global__ void unmap_kernel(const float* __restrict__ A,
                             const float* __restrict__ W,
                             const float* __restrict__ bias,
                             float* __restrict__ C)
{
    __shared__ float As[16][64];
    __shared__ float Bs[16][64];
    int tid = threadIdx.x;
    int rowBase = blockIdx.x * 64;
    int colBase = blockIdx.y * 64;
    int tx = tid & 15, ty = tid >> 4;
    int lr = tid >> 2, lk = (tid & 3) * 4;
    float acc[4][4] = {};
    for (int k0 = 0; k0 < D_; k0 += 16) {
        float4 av = *(const float4*)(A + (size_t)(rowBase + lr)*D_ + k0 + lk);
        float4 bv = *(const float4*)(W + (size_t)(colBase + lr)*D_ + k0 + lk);
        As[lk+0][lr] = av.x; As[lk+1][lr] = av.y; As[lk+2][lr] = av.z; As[lk+3][lr] = av.w;
        Bs[lk+0][lr] = bv.x; Bs[lk+1][lr] = bv.y; Bs[lk+2][lr] = bv.z; Bs[lk+3][lr] = bv.w;
        __syncthreads();
        #pragma unroll
        for (int kk = 0; kk < 16; kk++) {
            float a[4], bb[4];
            #pragma unroll
            for (int i = 0; i < 4; i++) a[i]  = As[kk][ty*4 + i];
            #pragma unroll
            for (int j = 0; j < 4; j++) bb[j] = Bs[kk][tx*4 + j];
            #pragma unroll
            for (int i = 0; i < 4; i++)
                #pragma unroll
                for (int j = 0; j < 4; j++)
                    acc[i][j] += a[i] * bb[j];
        }
        __syncthreads();
    }
    #pragma unroll
    for (int i = 0; i < 4; i++) {
        int rr = rowBase + ty*4 + i;
        int t = rr % T_, bb2 = rr / T_;
        #pragma unroll
        for (int j = 0; j < 4; j++) {
            int c = colBase + tx*4 + j;
            C[((size_t)t*B_ + bb2)*D_ + c] = acc[i][j] + bias[c];
        }
    }
}

// ---------------------------------------------------------------------------
extern "C" void kernel_launch(void* const* d_in, const int* in_sizes, int n_in,
                              void* d_out, int out_size)
{
    const float* z     = (const float*)d_in[0];
    const float* state = (const float*)d_in[1];
    const float* Wk    = (const float*)d_in[2];
    const float* Wq    = (const float*)d_in[3];
    const float* Wv    = (const float*)d_in[4];
    const float* ln_w  = (const float*)d_in[5];
    const float* ln_b  = (const float*)d_in[6];
    const float* ff_w1 = (const float*)d_in[7];
    const float* ff_b1 = (const float*)d_in[8];
    const float* ff_w2 = (const float*)d_in[9];
    const float* ff_b2 = (const float*)d_in[10];
    const float* sc_w  = (const float*)d_in[11];
    const float* sc_b  = (const float*)d_in[12];
    const float* um_w  = (const float*)d_in[13];
    const float* um_b  = (const float*)d_in[14];
    float* out = (float*)d_out;
    float* stout = out + YSZ;

    float *x, *Q, *K, *V, *att;
    cudaGetSymbolAddress((void**)&x,   g_x);
    cudaGetSymbolAddress((void**)&Q,   g_Q);
    cudaGetSymbolAddress((void**)&K,   g_K);
    cudaGetSymbolAddress((void**)&V,   g_V);
    cudaGetSymbolAddress((void**)&att, g_att);

    rotate_kernel<<<(B_*T_*64 + 255)/256, 256>>>(z, state, x, stout);

    for (int l = 0; l < L_; l++) {
        size_t wo = (size_t)l*D_*D_;
        qkv_kernel<<<dim3(ROWS/64, 6), 256>>>(x, Wq + wo, Wk + wo, Wv + wo,
                                              ln_w + l*D_, ln_b + l*D_, Q, K, V);
        attn_kernel<<<dim3(T_/16, B_), 256>>>(Q, K, V, state, l, att);
        state_kernel<<<dim3(2,2,B_), 256>>>(K, V, state, l, stout);
        ffn_kernel<<<ROWS/16, 256>>>(att,
                                     ff_w1 + wo, ff_b1 + l*D_,
                                     ff_w2 + wo, ff_b2 + l*D_,
                                     sc_w  + wo, sc_b  + l*D_,
                                     ln_w + l*D_, ln_b + l*D_, x);
    }
    unmap_kernel<<<dim3(ROWS/64, D_/64), 256>>>(x, um_w, um_b, out);
}

// round 4
// speedup vs baseline: 1.6127x; 1.6127x over previous
#include <cuda_runtime.h>
#include <math.h>

#define T_ 256
#define B_ 8
#define D_ 128
#define L_ 2
#define NC 8                 // chunks
#define CS 32                // chunk size
#define ROWS (B_*T_)         // 2048
#define STROW (L_*(D_*D_+D_)+1)  // 33025
#define STSEG (D_*D_+D_)     // 16512
#define YSZ (T_*B_*D_)

// ---------------- scratch ---------------------------------------------------
__device__ float g_x  [ROWS*D_];
__device__ float g_Q  [ROWS*D_];
__device__ float g_K  [ROWS*D_];
__device__ float g_V  [ROWS*D_];
__device__ float g_att[ROWS*D_];
__device__ float g_Sc [B_*NC*D_*D_];   // per-chunk K^T V
__device__ float g_zc [B_*NC*D_];      // per-chunk colsum K
__device__ float g_P  [B_*NC*D_*D_];   // exclusive prefix states (incl S0)
__device__ float g_Pz [B_*NC*D_];

// ---------------- rotate (RoPE) + transpose ---------------------------------
__global__ void rotate_kernel(const float* __restrict__ z,
                              const float* __restrict__ state,
                              float* __restrict__ x,
                              float* __restrict__ out_st)
{
    int idx = blockIdx.x * blockDim.x + threadIdx.x;
    if (idx >= B_*T_*64) return;
    int j = idx & 63;
    int t = (idx >> 6) % T_;
    int b = idx / (64 * T_);
    float ts  = state[b*STROW + (STROW-1)];
    float pos = ts + (float)t;
    float freq = expf((float)(2*j) * (-logf(10000.0f) / (float)D_));
    float ang = pos * freq;
    float s, c;
    sincosf(ang, &s, &c);
    const float* zr = z + ((size_t)t*B_ + b) * D_;
    float*       xr = x + ((size_t)b*T_ + t) * D_;
    float a0 = zr[j], a1 = zr[j+64];
    xr[j]    = a0*c - a1*s;
    xr[j+64] = a1*c + a0*s;
    if (t == 0 && j == 0)
        out_st[b*STROW + (STROW-1)] = ts + (float)T_;
}

// ---------------- fused LN + QKV GEMM (32-row tiles) -------------------------
// grid (ROWS/32, 6): y 0,1 -> Q(elu+1); 2,3 -> K(elu+1); 4,5 -> V
__global__ void qkv_kernel(const float* __restrict__ x,
                           const float* __restrict__ Wq,
                           const float* __restrict__ Wk,
                           const float* __restrict__ Wv,
                           const float* __restrict__ lnw,
                           const float* __restrict__ lnb,
                           float* __restrict__ Qo,
                           float* __restrict__ Ko,
                           float* __restrict__ Vo)
{
    __shared__ float Xs[128][33];   // [k][row]
    __shared__ float Ws[16][68];
    __shared__ float mu[32], rsd[32];
    int tid = threadIdx.x;
    int rowBase = blockIdx.x * 32;
    int sel = blockIdx.y;
    const float* W; float* out; int act;
    if (sel < 2)      { W = Wq; out = Qo; act = 1; }
    else if (sel < 4) { W = Wk; out = Ko; act = 1; }
    else              { W = Wv; out = Vo; act = 0; }
    int colBase = (sel & 1) * 64;

    int r = tid >> 3, p = tid & 7;
    {
        const float* src = x + (size_t)(rowBase + r)*D_ + p*16;
        #pragma unroll
        for (int i = 0; i < 4; i++) {
            float4 v = *(const float4*)(src + i*4);
            int k = p*16 + i*4;
            Xs[k+0][r]=v.x; Xs[k+1][r]=v.y; Xs[k+2][r]=v.z; Xs[k+3][r]=v.w;
        }
    }
    __syncthreads();
    if (tid < 32) {
        float s = 0.f, s2 = 0.f;
        #pragma unroll 8
        for (int k = 0; k < 128; k++) { float v = Xs[k][tid]; s += v; s2 += v*v; }
        float m = s * (1.0f/128.0f);
        mu[tid] = m;
        rsd[tid] = rsqrtf(fmaxf(s2*(1.0f/128.0f) - m*m, 0.0f) + 1e-5f);
    }
    __syncthreads();
    {
        float m = mu[r], rr = rsd[r];
        #pragma unroll
        for (int i = 0; i < 16; i++) {
            int k = p*16 + i;
            Xs[k][r] = (Xs[k][r] - m) * rr * lnw[k] + lnb[k];
        }
    }
    __syncthreads();

    int tx = tid & 15, ty = tid >> 4;
    float acc[2][4] = {};
    for (int k0 = 0; k0 < 128; k0 += 16) {
        {
            int c = tid & 63, kq = (tid >> 6) * 4;
            float4 w4 = *(const float4*)(W + (size_t)(colBase + c)*D_ + k0 + kq);
            Ws[kq+0][c]=w4.x; Ws[kq+1][c]=w4.y; Ws[kq+2][c]=w4.z; Ws[kq+3][c]=w4.w;
        }
        __syncthreads();
        #pragma unroll
        for (int kk = 0; kk < 16; kk++) {
            float a0 = Xs[k0+kk][ty*2];
            float a1 = Xs[k0+kk][ty*2+1];
            float4 b4 = *(const float4*)&Ws[kk][tx*4];
            acc[0][0]+=a0*b4.x; acc[0][1]+=a0*b4.y; acc[0][2]+=a0*b4.z; acc[0][3]+=a0*b4.w;
            acc[1][0]+=a1*b4.x; acc[1][1]+=a1*b4.y; acc[1][2]+=a1*b4.z; acc[1][3]+=a1*b4.w;
        }
        __syncthreads();
    }
    #pragma unroll
    for (int i = 0; i < 2; i++) {
        int rr2 = rowBase + ty*2 + i;
        #pragma unroll
        for (int j = 0; j < 4; j++) {
            float v = acc[i][j];
            if (act == 1) v = (v > 0.f) ? v + 1.0f : expf(v);
            out[(size_t)rr2*D_ + colBase + tx*4 + j] = v;
        }
    }
}

// ---------------- per-chunk state: Sc = Kc^T Vc, zc = colsum Kc --------------
// grid (4, NC, B): x -> tile (it = x&1 over i, lt = x>>1 over l)
__global__ void chunk_kernel(const float* __restrict__ Kg,
                             const float* __restrict__ Vg,
                             float* __restrict__ Sc,
                             float* __restrict__ zc)
{
    int tid = threadIdx.x;
    int it = blockIdx.x & 1, lt = blockIdx.x >> 1;
    int c = blockIdx.y, b = blockIdx.z;
    int iBase = it * 64, lBase = lt * 64;
    const float* Kb = Kg + ((size_t)b*T_ + c*CS) * D_;
    const float* Vb = Vg + ((size_t)b*T_ + c*CS) * D_;
    __shared__ float Ks[CS][68], Vs[CS][68];
    __shared__ float zsum[64];
    int r = tid >> 3, p = tid & 7;
    {
        const float* ks = Kb + (size_t)r*D_ + iBase + p*8;
        const float* vs = Vb + (size_t)r*D_ + lBase + p*8;
        *(float4*)&Ks[r][p*8]   = *(const float4*)ks;
        *(float4*)&Ks[r][p*8+4] = *(const float4*)(ks+4);
        *(float4*)&Vs[r][p*8]   = *(const float4*)vs;
        *(float4*)&Vs[r][p*8+4] = *(const float4*)(vs+4);
    }
    __syncthreads();
    if (lt == 0 && tid < 64) {
        float s = 0.f;
        #pragma unroll
        for (int kk = 0; kk < CS; kk++) s += Ks[kk][tid];
        zsum[tid] = s;
    }
    int tx = tid & 15, ty = tid >> 4;
    float acc[4][4] = {};
    #pragma unroll 4
    for (int kk = 0; kk < CS; kk++) {
        float a[4], bb[4];
        #pragma unroll
        for (int i = 0; i < 4; i++) a[i]  = Ks[kk][ty*4 + i];
        #pragma unroll
        for (int j = 0; j < 4; j++) bb[j] = Vs[kk][tx*4 + j];
        #pragma unroll
        for (int i = 0; i < 4; i++)
            #pragma unroll
            for (int j = 0; j < 4; j++)
                acc[i][j] += a[i] * bb[j];
    }
    float* dst = Sc + (((size_t)(b*NC + c))*D_)*D_;
    #pragma unroll
    for (int i = 0; i < 4; i++) {
        int ii = iBase + ty*4 + i;
        #pragma unroll
        for (int j = 0; j < 4; j++)
            dst[(size_t)ii*D_ + lBase + tx*4 + j] = acc[i][j];
    }
    if (lt == 0 && tid < 64)
        zc[((size_t)(b*NC + c))*D_ + iBase + tid] = zsum[tid];
}

// ---------------- prefix scan over chunks + final state ----------------------
// P[b,c] = S0 + sum_{c'<c} Sc ; stout = S0 + sum_all. Same for z.
__global__ void scan_kernel(const float* __restrict__ Sc,
                            const float* __restrict__ zc,
                            const float* __restrict__ state,
                            int layer,
                            float* __restrict__ P,
                            float* __restrict__ Pz,
                            float* __restrict__ stout)
{
    int b = blockIdx.y;
    int e = blockIdx.x * blockDim.x + threadIdx.x;
    const float* s0 = state + (size_t)b*STROW + (size_t)layer*STSEG;
    float* so = stout + (size_t)b*STROW + (size_t)layer*STSEG;
    if (e < D_*D_) {
        float vals[NC];
        #pragma unroll
        for (int c = 0; c < NC; c++)
            vals[c] = Sc[(((size_t)(b*NC + c))*D_)*D_ + e];
        float run = s0[e];
        #pragma unroll
        for (int c = 0; c < NC; c++) {
            P[(((size_t)(b*NC + c))*D_)*D_ + e] = run;
            run += vals[c];
        }
        so[e] = run;
    } else if (e < D_*D_ + D_) {
        int i = e - D_*D_;
        float vals[NC];
        #pragma unroll
        for (int c = 0; c < NC; c++)
            vals[c] = zc[((size_t)(b*NC + c))*D_ + i];
        float run = s0[e];
        #pragma unroll
        for (int c = 0; c < NC; c++) {
            Pz[((size_t)(b*NC + c))*D_ + i] = run;
            run += vals[c];
        }
        so[e] = run;
    }
}

// ---------------- attention output -------------------------------------------
// out[t,l] = (causal-intra(QK^T)V + Q P[c]) / (rowsum intra + Q.Pz[c] + 1e-5)
// grid (4 colquarters, NC, B), 256 threads, 32 rows x 32 cols per block.
__global__ void attnout_kernel(const float* __restrict__ Qg,
                               const float* __restrict__ Kg,
                               const float* __restrict__ Vg,
                               const float* __restrict__ P,
                               const float* __restrict__ Pz,
                               float* __restrict__ O)
{
    __shared__ float Qs[CS][132];
    __shared__ float Kc[CS][132];
    __shared__ float Vc[CS][36];
    __shared__ float As[CS][36];
    __shared__ float Ps[CS][36];
    __shared__ float zz[D_];
    __shared__ float den[CS];
    int tid = threadIdx.x;
    int colBase = blockIdx.x * 32;
    int c = blockIdx.y, b = blockIdx.z;
    const float* Qb = Qg + ((size_t)b*T_ + c*CS) * D_;
    const float* Kb = Kg + ((size_t)b*T_ + c*CS) * D_;
    const float* Vb = Vg + ((size_t)b*T_ + c*CS) * D_;
    const float* Pb = P  + (((size_t)(b*NC + c))*D_)*D_;
    const float* Pzb= Pz + ((size_t)(b*NC + c))*D_;

    int r = tid >> 3, p = tid & 7;
    {
        const float* qs = Qb + (size_t)r*D_ + p*16;
        const float* ks = Kb + (size_t)r*D_ + p*16;
        #pragma unroll
        for (int i = 0; i < 4; i++) {
            *(float4*)&Qs[r][p*16 + i*4] = *(const float4*)(qs + i*4);
            *(float4*)&Kc[r][p*16 + i*4] = *(const float4*)(ks + i*4);
        }
        *(float4*)&Vc[r][p*4] = *(const float4*)(Vb + (size_t)r*D_ + colBase + p*4);
    }
    if (tid < D_) zz[tid] = Pzb[tid];
    __syncthreads();

    // intra-chunk A = causal(Q Kc^T): 4 dots per thread
    {
        int t = tid >> 3;
        int u0 = (tid & 7) * 4;
        float a[4] = {};
        #pragma unroll 4
        for (int k = 0; k < 128; k += 4) {
            float4 q4 = *(const float4*)&Qs[t][k];
            #pragma unroll
            for (int uu = 0; uu < 4; uu++) {
                float4 k4 = *(const float4*)&Kc[u0+uu][k];
                a[uu] += q4.x*k4.x + q4.y*k4.y + q4.z*k4.z + q4.w*k4.w;
            }
        }
        #pragma unroll
        for (int uu = 0; uu < 4; uu++)
            As[t][u0+uu] = (u0+uu <= t) ? a[uu] : 0.f;
    }
    __syncthreads();
    if (tid < CS) {
        float s = 0.f;
        #pragma unroll
        for (int u = 0; u < CS; u++) s += As[tid][u];
        #pragma unroll 8
        for (int k = 0; k < 128; k++) s += Qs[tid][k] * zz[k];
        den[tid] = s;
    }

    int t = tid >> 3, col0 = (tid & 7) * 4;
    float acc[4] = {};
    #pragma unroll 4
    for (int u = 0; u < CS; u++) {
        float a = As[t][u];
        float4 v4 = *(const float4*)&Vc[u][col0];
        acc[0]+=a*v4.x; acc[1]+=a*v4.y; acc[2]+=a*v4.z; acc[3]+=a*v4.w;
    }
    // Q @ P[c]: stream P in 32-row slabs
    for (int ks = 0; ks < 4; ks++) {
        __syncthreads();
        *(float4*)&Ps[r][p*4] = *(const float4*)(Pb + (size_t)(ks*32 + r)*D_ + colBase + p*4);
        __syncthreads();
        #pragma unroll 4
        for (int kk = 0; kk < 32; kk++) {
            float a = Qs[t][ks*32 + kk];
            float4 v4 = *(const float4*)&Ps[kk][col0];
            acc[0]+=a*v4.x; acc[1]+=a*v4.y; acc[2]+=a*v4.z; acc[3]+=a*v4.w;
        }
    }
    float inv = 1.0f / (den[t] + 1e-5f);
    float* orow = O + ((size_t)b*T_ + c*CS + t)*D_ + colBase + col0;
    #pragma unroll
    for (int j = 0; j < 4; j++) orow[j] = acc[j] * inv;
}

// ---------------- fused FFN + skip (8-row tiles) ------------------------------
__global__ void ffn_kernel(const float* __restrict__ att,
                           const float* __restrict__ w1, const float* __restrict__ b1,
                           const float* __restrict__ w2, const float* __restrict__ b2,
                           const float* __restrict__ scw, const float* __restrict__ scb,
                           const float* __restrict__ lnw, const float* __restrict__ lnb,
                           float* x)
{
    __shared__ float Aat[8][132];
    __shared__ float Hs[8][132];
    __shared__ float Ws[16][132];
    __shared__ float mu[8], rsd[8];
    int tid = threadIdx.x;
    int rowBase = blockIdx.x * 8;
    int tyr = tid >> 5;          // 8 rows
    int txc = tid & 31;          // 32 col groups of 4
    int r = tid >> 5, p = tid & 31;

    *(float4*)&Aat[r][p*4] = *(const float4*)(att + (size_t)(rowBase + r)*D_ + p*4);
    __syncthreads();

    float acc[4] = {};
    for (int k0 = 0; k0 < 128; k0 += 16) {
        {
            int cc = tid >> 1, kq = (tid & 1) * 8;
            const float* wp = w1 + (size_t)cc*D_ + k0 + kq;
            float4 wa = *(const float4*)wp, wb = *(const float4*)(wp + 4);
            Ws[kq+0][cc]=wa.x; Ws[kq+1][cc]=wa.y; Ws[kq+2][cc]=wa.z; Ws[kq+3][cc]=wa.w;
            Ws[kq+4][cc]=wb.x; Ws[kq+5][cc]=wb.y; Ws[kq+6][cc]=wb.z; Ws[kq+7][cc]=wb.w;
        }
        __syncthreads();
        #pragma unroll
        for (int kk = 0; kk < 16; kk++) {
            float a = Aat[tyr][k0 + kk];
            float4 c4 = *(const float4*)&Ws[kk][txc*4];
            acc[0]+=a*c4.x; acc[1]+=a*c4.y; acc[2]+=a*c4.z; acc[3]+=a*c4.w;
        }
        __syncthreads();
    }
    #pragma unroll
    for (int j = 0; j < 4; j++)
        Hs[tyr][txc*4 + j] = fmaxf(acc[j] + b1[txc*4 + j], 0.0f);

    float t2[4] = {};
    for (int k0 = 0; k0 < 128; k0 += 16) {
        {
            int cc = tid >> 1, kq = (tid & 1) * 8;
            const float* wp = w2 + (size_t)cc*D_ + k0 + kq;
            float4 wa = *(const float4*)wp, wb = *(const float4*)(wp + 4);
            Ws[kq+0][cc]=wa.x; Ws[kq+1][cc]=wa.y; Ws[kq+2][cc]=wa.z; Ws[kq+3][cc]=wa.w;
            Ws[kq+4][cc]=wb.x; Ws[kq+5][cc]=wb.y; Ws[kq+6][cc]=wb.z; Ws[kq+7][cc]=wb.w;
        }
        __syncthreads();
        #pragma unroll
        for (int kk = 0; kk < 16; kk++) {
            float a = Hs[tyr][k0 + kk];
            float4 c4 = *(const float4*)&Ws[kk][txc*4];
            t2[0]+=a*c4.x; t2[1]+=a*c4.y; t2[2]+=a*c4.z; t2[3]+=a*c4.w;
        }
        __syncthreads();
    }
    #pragma unroll
    for (int j = 0; j < 4; j++) t2[j] = fmaxf(t2[j] + b2[txc*4 + j], 0.0f);

    *(float4*)&Aat[r][p*4] = *(const float4*)(x + (size_t)(rowBase + r)*D_ + p*4);
    __syncthreads();
    if (tid < 8) {
        float s = 0.f, s2 = 0.f;
        #pragma unroll 8
        for (int k = 0; k < 128; k++) { float v = Aat[tid][k]; s += v; s2 += v*v; }
        float m = s * (1.0f/128.0f);
        mu[tid] = m;
        rsd[tid] = rsqrtf(fmaxf(s2*(1.0f/128.0f) - m*m, 0.0f) + 1e-5f);
    }
    __syncthreads();
    {
        float m = mu[r], rr = rsd[r];
        #pragma unroll
        for (int i = 0; i < 4; i++) {
            int k = p*4 + i;
            Aat[r][k] = (Aat[r][k] - m) * rr * lnw[k] + lnb[k];
        }
    }
    __syncthreads();

    float a3[4] = {};
    for (int k0 = 0; k0 < 128; k0 += 16) {
        {
            int cc = tid >> 1, kq = (tid & 1) * 8;
            const float* wp = scw + (size_t)cc*D_ + k0 + kq;
            float4 wa = *(const float4*)wp, wb = *(const float4*)(wp + 4);
            Ws[kq+0][cc]=wa.x; Ws[kq+1][cc]=wa.y; Ws[kq+2][cc]=wa.z; Ws[kq+3][cc]=wa.w;
            Ws[kq+4][cc]=wb.x; Ws[kq+5][cc]=wb.y; Ws[kq+6][cc]=wb.z; Ws[kq+7][cc]=wb.w;
        }
        __syncthreads();
        #pragma unroll
        for (int kk = 0; kk < 16; kk++) {
            float a = Aat[tyr][k0 + kk];
            float4 c4 = *(const float4*)&Ws[kk][txc*4];
            a3[0]+=a*c4.x; a3[1]+=a*c4.y; a3[2]+=a*c4.z; a3[3]+=a*c4.w;
        }
        __syncthreads();
    }
    float* xo = x + (size_t)(rowBase + tyr)*D_ + txc*4;
    #pragma unroll
    for (int j = 0; j < 4; j++)
        xo[j] = a3[j] + scb[txc*4 + j] + t2[j];
}

// ---------------- unmap GEMM (32-row tiles, scatter) --------------------------
__global__ void unmap_kernel(const float* __restrict__ A,
                             const float* __restrict__ W,
                             const float* __restrict__ bias,
                             float* __restrict__ C)
{
    __shared__ float Xs[128][33];
    __shared__ float Ws[16][68];
    int tid = threadIdx.x;
    int rowBase = blockIdx.x * 32;
    int colBase = blockIdx.y * 64;
    int r = tid >> 3, p = tid & 7;
    {
        const float* src = A + (size_t)(rowBase + r)*D_ + p*16;
        #pragma unroll
        for (int i = 0; i < 4; i++) {
            float4 v = *(const float4*)(src + i*4);
            int k = p*16 + i*4;
            Xs[k+0][r]=v.x; Xs[k+1][r]=v.y; Xs[k+2][r]=v.z; Xs[k+3][r]=v.w;
        }
    }
    __syncthreads();
    int tx = tid & 15, ty = tid >> 4;
    float acc[2][4] = {};
    for (int k0 = 0; k0 < 128; k0 += 16) {
        {
            int cc = tid & 63, kq = (tid >> 6) * 4;
            float4 w4 = *(const float4*)(W + (size_t)(colBase + cc)*D_ + k0 + kq);
            Ws[kq+0][cc]=w4.x; Ws[kq+1][cc]=w4.y; Ws[kq+2][cc]=w4.z; Ws[kq+3][cc]=w4.w;
        }
        __syncthreads();
        #pragma unroll
        for (int kk = 0; kk < 16; kk++) {
            float a0 = Xs[k0+kk][ty*2];
            float a1 = Xs[k0+kk][ty*2+1];
            float4 b4 = *(const float4*)&Ws[kk][tx*4];
            acc[0][0]+=a0*b4.x; acc[0][1]+=a0*b4.y; acc[0][2]+=a0*b4.z; acc[0][3]+=a0*b4.w;
            acc[1][0]+=a1*b4.x; acc[1][1]+=a1*b4.y; acc[1][2]+=a1*b4.z; acc[1][3]+=a1*b4.w;
        }
        __syncthreads();
    }
    #pragma unroll
    for (int i = 0; i < 2; i++) {
        int rr = rowBase + ty*2 + i;
        int t = rr % T_, bb = rr / T_;
        #pragma unroll
        for (int j = 0; j < 4; j++) {
            int cc = colBase + tx*4 + j;
            C[((size_t)t*B_ + bb)*D_ + cc] = acc[i][j] + bias[cc];
        }
    }
}

// ---------------------------------------------------------------------------
extern "C" void kernel_launch(void* const* d_in, const int* in_sizes, int n_in,
                              void* d_out, int out_size)
{
    const float* z     = (const float*)d_in[0];
    const float* state = (const float*)d_in[1];
    const float* Wk    = (const float*)d_in[2];
    const float* Wq    = (const float*)d_in[3];
    const float* Wv    = (const float*)d_in[4];
    const float* ln_w  = (const float*)d_in[5];
    const float* ln_b  = (const float*)d_in[6];
    const float* ff_w1 = (const float*)d_in[7];
    const float* ff_b1 = (const float*)d_in[8];
    const float* ff_w2 = (const float*)d_in[9];
    const float* ff_b2 = (const float*)d_in[10];
    const float* sc_w  = (const float*)d_in[11];
    const float* sc_b  = (const float*)d_in[12];
    const float* um_w  = (const float*)d_in[13];
    const float* um_b  = (const float*)d_in[14];
    float* out = (float*)d_out;
    float* stout = out + YSZ;

    float *x, *Q, *K, *V, *att, *Sc, *zc, *P, *Pz;
    cudaGetSymbolAddress((void**)&x,   g_x);
    cudaGetSymbolAddress((void**)&Q,   g_Q);
    cudaGetSymbolAddress((void**)&K,   g_K);
    cudaGetSymbolAddress((void**)&V,   g_V);
    cudaGetSymbolAddress((void**)&att, g_att);
    cudaGetSymbolAddress((void**)&Sc,  g_Sc);
    cudaGetSymbolAddress((void**)&zc,  g_zc);
    cudaGetSymbolAddress((void**)&P,   g_P);
    cudaGetSymbolAddress((void**)&Pz,  g_Pz);

    rotate_kernel<<<(B_*T_*64 + 255)/256, 256>>>(z, state, x, stout);

    for (int l = 0; l < L_; l++) {
        size_t wo = (size_t)l*D_*D_;
        qkv_kernel<<<dim3(ROWS/32, 6), 256>>>(x, Wq + wo, Wk + wo, Wv + wo,
                                              ln_w + l*D_, ln_b + l*D_, Q, K, V);
        chunk_kernel<<<dim3(4, NC, B_), 256>>>(K, V, Sc, zc);
        scan_kernel<<<dim3((STSEG + 255)/256, B_), 256>>>(Sc, zc, state, l, P, Pz, stout);
        attnout_kernel<<<dim3(4, NC, B_), 256>>>(Q, K, V, P, Pz, att);
        ffn_kernel<<<ROWS/8, 256>>>(att,
                                    ff_w1 + wo, ff_b1 + l*D_,
                                    ff_w2 + wo, ff_b2 + l*D_,
                                    sc_w  + wo, sc_b  + l*D_,
                                    ln_w + l*D_, ln_b + l*D_, x);
    }
    unmap_kernel<<<dim3(ROWS/32, D_/64), 256>>>(x, um_w, um_b, out);
}